// round 1
// baseline (speedup 1.0000x reference)
#include <cuda_runtime.h>

// Problem constants
#define Bc  32
#define Nc  128
#define Tc  96
#define Hc  64
#define TFc 24

// One block per batch element. All node-dimension computation collapses because
// A_norm = ones/N (complete graph + self loops) => GCN output is node-constant.

__global__ __launch_bounds__(128, 1)
void gde_kernel(const float* __restrict__ x,
                const float* __restrict__ W_s1, const float* __restrict__ b_s1,
                const float* __restrict__ W_s2, const float* __restrict__ b_s2,
                const float* __restrict__ Wa1,  const float* __restrict__ ba1,
                const float* __restrict__ Wa2,  const float* __restrict__ ba2,
                const float* __restrict__ W_ih, const float* __restrict__ b_ih,
                const float* __restrict__ b_hh,
                const float* __restrict__ W_o1, const float* __restrict__ b_o1,
                const float* __restrict__ W_o2, const float* __restrict__ b_o2,
                const float* __restrict__ W_out,const float* __restrict__ b_out,
                float* __restrict__ out)
{
    __shared__ float s_mx[Tc];
    __shared__ float s_h2[Tc][Hc];          // 24 KB
    __shared__ float s_ws1[Hc], s_bs1[Hc];
    __shared__ float s_att[Tc];
    __shared__ float s_w[Tc];
    __shared__ float s_nf[Hc];
    __shared__ float s_gi[3 * Hc];
    __shared__ float s_y[Hc], s_k1[Hc], s_k2[Hc], s_k3[Hc], s_tmp[Hc], s_u[Hc];
    __shared__ float s_pred[TFc];
    __shared__ float s_red[4];

    const int tid = threadIdx.x;
    const int b   = blockIdx.x;
    const float* xb = x + b * (Nc * Tc);

    // ---- phase 0: small weights to shared ----
    if (tid < Hc) { s_ws1[tid] = W_s1[tid]; s_bs1[tid] = b_s1[tid]; }

    // ---- phase 1: mean over nodes (coalesced along t) ----
    if (tid < Tc) {
        float s = 0.f;
        #pragma unroll 8
        for (int n = 0; n < Nc; n++) s += xb[n * Tc + tid];
        s_mx[tid] = s * (1.0f / Nc);
    }
    __syncthreads();

    // ---- phase 2a: h2[t][h] = relu( sum_k relu(mx*Ws1+bs1) * Ws2[k][h] + bs2[h] ) ----
    for (int o = tid; o < Tc * Hc; o += 128) {
        int t = o >> 6, h = o & 63;
        float mx  = s_mx[t];
        float acc = b_s2[h];
        #pragma unroll 8
        for (int k = 0; k < Hc; k++) {
            float h1 = fmaxf(fmaf(mx, s_ws1[k], s_bs1[k]), 0.f);
            acc = fmaf(h1, W_s2[k * Hc + h], acc);
        }
        s_h2[t][h] = fmaxf(acc, 0.f);
    }
    if (tid < Tc) s_att[tid] = ba2[0];
    __syncthreads();

    // ---- phase 2b: attention logits att[t] = sum_h tanh(h2@Wa1+ba1)[h]*Wa2[h] + ba2 ----
    for (int o = tid; o < Tc * Hc; o += 128) {
        int t = o >> 6, h = o & 63;
        float q = ba1[h];
        #pragma unroll 8
        for (int k = 0; k < Hc; k++) q = fmaf(s_h2[t][k], Wa1[k * Hc + h], q);
        float v = tanhf(q) * Wa2[h];
        // t is uniform across the warp -> reduce in-warp, one atomic per warp
        #pragma unroll
        for (int off = 16; off; off >>= 1) v += __shfl_xor_sync(0xffffffffu, v, off);
        if ((tid & 31) == 0) atomicAdd(&s_att[t], v);
    }
    __syncthreads();

    // ---- phase 2c: softmax over t (warp 0, 3 values per lane) ----
    if (tid < 32) {
        float a0 = s_att[tid], a1 = s_att[tid + 32], a2 = s_att[tid + 64];
        float m = fmaxf(a0, fmaxf(a1, a2));
        #pragma unroll
        for (int off = 16; off; off >>= 1) m = fmaxf(m, __shfl_xor_sync(0xffffffffu, m, off));
        float e0 = expf(a0 - m), e1 = expf(a1 - m), e2 = expf(a2 - m);
        float s = e0 + e1 + e2;
        #pragma unroll
        for (int off = 16; off; off >>= 1) s += __shfl_xor_sync(0xffffffffu, s, off);
        float inv = 1.f / s;
        s_w[tid] = e0 * inv; s_w[tid + 32] = e1 * inv; s_w[tid + 64] = e2 * inv;
    }
    __syncthreads();

    // ---- phase 2d: nf[h] = sum_t h2[t][h] * w[t] ----
    if (tid < Hc) {
        float acc = 0.f;
        #pragma unroll 8
        for (int t = 0; t < Tc; t++) acc = fmaf(s_h2[t][tid], s_w[t], acc);
        s_nf[tid] = acc;
    }
    __syncthreads();

    // ---- phase 2e: GRU (h0 = 0) ----
    for (int j = tid; j < 3 * Hc; j += 128) {
        const float4* row = (const float4*)(W_ih + j * Hc);
        float acc = b_ih[j];
        #pragma unroll
        for (int k4 = 0; k4 < Hc / 4; k4++) {
            float4 w4 = row[k4];
            acc = fmaf(w4.x, s_nf[4 * k4 + 0], acc);
            acc = fmaf(w4.y, s_nf[4 * k4 + 1], acc);
            acc = fmaf(w4.z, s_nf[4 * k4 + 2], acc);
            acc = fmaf(w4.w, s_nf[4 * k4 + 3], acc);
        }
        s_gi[j] = acc;
    }
    __syncthreads();
    if (tid < Hc) {
        float r = 1.f / (1.f + expf(-(s_gi[tid]          + b_hh[tid])));
        float z = 1.f / (1.f + expf(-(s_gi[Hc + tid]     + b_hh[Hc + tid])));
        float n = tanhf(s_gi[2 * Hc + tid] + r * b_hh[2 * Hc + tid]);
        s_y[tid] = (1.f - z) * n;
    }
    __syncthreads();

    // ---- phase 3: ODE. Thread h keeps W_o1[:,h], W_o2[:,h] in registers ----
    float wo1[Hc], wo2[Hc];
    float bo1 = 0.f, bo2 = 0.f, wout = 0.f;
    if (tid < Hc) {
        #pragma unroll
        for (int k = 0; k < Hc; k++) {
            wo1[k] = W_o1[k * Hc + tid];
            wo2[k] = W_o2[k * Hc + tid];
        }
        bo1 = b_o1[tid]; bo2 = b_o2[tid]; wout = W_out[tid];
    }
    const float bout = b_out[0];

    const float dt    = 24.0f / 23.0f;
    const float third = 1.0f / 3.0f;

    // pred[tf] = dot(y, W_out) + b_out   (all threads call; has a barrier inside)
    #define PRED_DOT(TF_IDX)                                                     \
        {                                                                        \
            float v = (tid < Hc) ? s_y[tid] * wout : 0.f;                        \
            _Pragma("unroll")                                                    \
            for (int off = 16; off; off >>= 1)                                   \
                v += __shfl_xor_sync(0xffffffffu, v, off);                       \
            if ((tid & 31) == 0) s_red[tid >> 5] = v;                            \
            __syncthreads();                                                     \
            if (tid == 0) s_pred[TF_IDX] = s_red[0] + s_red[1] + bout;           \
        }

    #define MATMUL_TANH(INSM, WREG, BIAS, OUTSM)                                 \
        if (tid < Hc) {                                                          \
            float a = BIAS;                                                      \
            _Pragma("unroll")                                                    \
            for (int k = 0; k < Hc; k++) a = fmaf(INSM[k], WREG[k], a);          \
            OUTSM[tid] = tanhf(a);                                               \
        }                                                                        \
        __syncthreads();

    PRED_DOT(0);
    __syncthreads();

    for (int s = 1; s < TFc; s++) {
        // k1 = f(y)
        MATMUL_TANH(s_y,   wo1, bo1, s_u);
        MATMUL_TANH(s_u,   wo2, bo2, s_k1);
        // k2 = f(y + dt*k1/3)
        if (tid < Hc) s_tmp[tid] = s_y[tid] + dt * third * s_k1[tid];
        __syncthreads();
        MATMUL_TANH(s_tmp, wo1, bo1, s_u);
        MATMUL_TANH(s_u,   wo2, bo2, s_k2);
        // k3 = f(y + dt*(k2 - k1/3))
        if (tid < Hc) s_tmp[tid] = s_y[tid] + dt * (s_k2[tid] - third * s_k1[tid]);
        __syncthreads();
        MATMUL_TANH(s_tmp, wo1, bo1, s_u);
        MATMUL_TANH(s_u,   wo2, bo2, s_k3);
        // k4 = f(y + dt*(k1 - k2 + k3))
        if (tid < Hc) s_tmp[tid] = s_y[tid] + dt * (s_k1[tid] - s_k2[tid] + s_k3[tid]);
        __syncthreads();
        MATMUL_TANH(s_tmp, wo1, bo1, s_u);
        MATMUL_TANH(s_u,   wo2, bo2, s_tmp);          // k4 lives in s_tmp
        // y += dt/8 * (k1 + 3*(k2+k3) + k4)
        if (tid < Hc)
            s_y[tid] = s_y[tid] + dt * 0.125f *
                       (s_k1[tid] + 3.f * (s_k2[tid] + s_k3[tid]) + s_tmp[tid]);
        __syncthreads();
        PRED_DOT(s);
        __syncthreads();
    }
    __syncthreads();

    // ---- output: out[b][n][tf] = pred[tf] (node-constant) ----
    float* ob = out + b * (Nc * TFc);
    for (int i = tid; i < Nc * TFc; i += 128) {
        ob[i] = s_pred[i % TFc];
    }
}

extern "C" void kernel_launch(void* const* d_in, const int* in_sizes, int n_in,
                              void* d_out, int out_size)
{
    // metadata order: x, W_s1, b_s1, W_s2, b_s2, Wa1, ba1, Wa2, ba2,
    //                 W_ih, W_hh(unused), b_ih, b_hh, W_o1, b_o1, W_o2, b_o2, W_out, b_out
    const float* x     = (const float*)d_in[0];
    const float* W_s1  = (const float*)d_in[1];
    const float* b_s1  = (const float*)d_in[2];
    const float* W_s2  = (const float*)d_in[3];
    const float* b_s2  = (const float*)d_in[4];
    const float* Wa1   = (const float*)d_in[5];
    const float* ba1   = (const float*)d_in[6];
    const float* Wa2   = (const float*)d_in[7];
    const float* ba2   = (const float*)d_in[8];
    const float* W_ih  = (const float*)d_in[9];
    const float* b_ih  = (const float*)d_in[11];
    const float* b_hh  = (const float*)d_in[12];
    const float* W_o1  = (const float*)d_in[13];
    const float* b_o1  = (const float*)d_in[14];
    const float* W_o2  = (const float*)d_in[15];
    const float* b_o2  = (const float*)d_in[16];
    const float* W_out = (const float*)d_in[17];
    const float* b_out = (const float*)d_in[18];

    gde_kernel<<<Bc, 128>>>(x, W_s1, b_s1, W_s2, b_s2, Wa1, ba1, Wa2, ba2,
                            W_ih, b_ih, b_hh, W_o1, b_o1, W_o2, b_o2,
                            W_out, b_out, (float*)d_out);
}

// round 3
// speedup vs baseline: 2.1715x; 2.1715x over previous
#include <cuda_runtime.h>

#define Bc  32
#define Nc  128
#define Tc  96
#define Hc  64
#define TFc 24

// Dynamic shared: [Tc*Hc] h1 buffer, [Tc*Hc] h2 buffer = 48KB exactly.
extern __shared__ float dyn_smem[];

// Overflow-safe fast tanh: tanh(x) = sign(x) * (1-e^{-2|x|})/(1+e^{-2|x|})
__device__ __forceinline__ float ftanh(float x) {
    float ax = fabsf(x);
    float e  = __expf(-2.0f * ax);
    float t  = __fdividef(1.0f - e, 1.0f + e);
    return copysignf(t, x);
}
__device__ __forceinline__ float fsigm(float x) {
    return __fdividef(1.0f, 1.0f + __expf(-x));
}

// 64-dot from an aligned shared vector (float4 broadcast loads) against a
// register-resident weight column, 4 accumulators to break the FFMA chain.
__device__ __forceinline__ float mm64(const float* v, const float* w, float bias) {
    const float4* v4 = (const float4*)v;
    float a0 = 0.f, a1 = 0.f, a2 = 0.f, a3 = 0.f;
    #pragma unroll
    for (int q = 0; q < 16; q++) {
        float4 xv = v4[q];
        a0 = fmaf(xv.x, w[4 * q + 0], a0);
        a1 = fmaf(xv.y, w[4 * q + 1], a1);
        a2 = fmaf(xv.z, w[4 * q + 2], a2);
        a3 = fmaf(xv.w, w[4 * q + 3], a3);
    }
    return bias + ((a0 + a1) + (a2 + a3));
}

#define ODEBAR() asm volatile("bar.sync 1, 64;" ::: "memory")

__global__ __launch_bounds__(128, 1)
void gde_kernel(const float* __restrict__ x,
                const float* __restrict__ W_s1, const float* __restrict__ b_s1,
                const float* __restrict__ W_s2, const float* __restrict__ b_s2,
                const float* __restrict__ Wa1,  const float* __restrict__ ba1,
                const float* __restrict__ Wa2,  const float* __restrict__ ba2,
                const float* __restrict__ W_ih, const float* __restrict__ b_ih,
                const float* __restrict__ b_hh,
                const float* __restrict__ W_o1, const float* __restrict__ b_o1,
                const float* __restrict__ W_o2, const float* __restrict__ b_o2,
                const float* __restrict__ W_out,const float* __restrict__ b_out,
                float* __restrict__ out)
{
    __shared__ __align__(16) float s_mx[Tc];
    __shared__ __align__(16) float s_ws1[Hc], s_bs1[Hc];
    __shared__ __align__(16) float s_att[Tc], s_w[Tc];
    __shared__ __align__(16) float s_nf[Hc];
    __shared__ __align__(16) float s_gi[3 * Hc];
    __shared__ __align__(16) float s_in[Hc], s_u[Hc];
    __shared__ __align__(16) float s_traj[TFc][Hc];
    __shared__ __align__(16) float s_wout[Hc];
    __shared__ float s_pred[TFc];

    float* s_h1 = dyn_smem;            // [Tc][Hc], indexed by k
    float* s_h2 = dyn_smem + Tc * Hc;  // [Tc][Hc], indexed by h

    const int tid = threadIdx.x;
    const int b   = blockIdx.x;
    const float* xb = x + b * (Nc * Tc);
    const float bout = b_out[0];

    // ---- phase 0: small weights + mean over nodes (coalesced along t) ----
    if (tid < Hc) {
        s_ws1[tid]  = W_s1[tid];
        s_bs1[tid]  = b_s1[tid];
        s_wout[tid] = W_out[tid];
    }
    if (tid < Tc) {
        float s = 0.f;
        #pragma unroll 8
        for (int n = 0; n < Nc; n++) s += xb[n * Tc + tid];
        s_mx[tid] = s * (1.0f / Nc);
    }
    __syncthreads();

    // ---- h1[t][k] = relu(mx[t]*Ws1[k] + bs1[k])  (thread: k fixed) ----
    {
        int k = tid & 63;
        float wk = s_ws1[k], bk = s_bs1[k];
        for (int t = tid >> 6; t < Tc; t += 2)
            s_h1[t * Hc + k] = fmaxf(fmaf(s_mx[t], wk, bk), 0.f);
    }
    __syncthreads();

    // ---- 2a: h2[t][h] = relu(h1[t] . Ws2[:,h] + bs2[h])  (h fixed, col in regs) ----
    {
        int h = tid & 63;
        float wcol[Hc];
        #pragma unroll
        for (int k = 0; k < Hc; k++) wcol[k] = W_s2[k * Hc + h];
        float bias = b_s2[h];
        for (int t = tid >> 6; t < Tc; t += 2) {
            float a = mm64(&s_h1[t * Hc], wcol, bias);
            s_h2[t * Hc + h] = fmaxf(a, 0.f);
        }
    }
    if (tid < Tc) s_att[tid] = ba2[0];
    __syncthreads();

    // ---- 2b: att[t] = sum_h tanh(h2[t].Wa1[:,h]+ba1[h]) * Wa2[h] + ba2 ----
    {
        int h = tid & 63;
        float wcol[Hc];
        #pragma unroll
        for (int k = 0; k < Hc; k++) wcol[k] = Wa1[k * Hc + h];
        float bias = ba1[h];
        float wa2  = Wa2[h];
        for (int t = tid >> 6; t < Tc; t += 2) {
            float q = mm64(&s_h2[t * Hc], wcol, bias);
            float v = ftanh(q) * wa2;
            #pragma unroll
            for (int off = 16; off; off >>= 1) v += __shfl_xor_sync(0xffffffffu, v, off);
            if ((tid & 31) == 0) atomicAdd(&s_att[t], v);
        }
    }
    __syncthreads();

    // ---- softmax over t (warp 0, 3 values per lane) ----
    if (tid < 32) {
        float a0 = s_att[tid], a1 = s_att[tid + 32], a2 = s_att[tid + 64];
        float m = fmaxf(a0, fmaxf(a1, a2));
        #pragma unroll
        for (int off = 16; off; off >>= 1) m = fmaxf(m, __shfl_xor_sync(0xffffffffu, m, off));
        float e0 = __expf(a0 - m), e1 = __expf(a1 - m), e2 = __expf(a2 - m);
        float s = e0 + e1 + e2;
        #pragma unroll
        for (int off = 16; off; off >>= 1) s += __shfl_xor_sync(0xffffffffu, s, off);
        float inv = __fdividef(1.f, s);
        s_w[tid] = e0 * inv; s_w[tid + 32] = e1 * inv; s_w[tid + 64] = e2 * inv;
    }
    __syncthreads();

    // ---- nf[h] = sum_t h2[t][h] * w[t] ----
    if (tid < Hc) {
        float a0 = 0.f, a1 = 0.f, a2 = 0.f, a3 = 0.f;
        #pragma unroll
        for (int t = 0; t < Tc; t += 4) {
            a0 = fmaf(s_h2[(t + 0) * Hc + tid], s_w[t + 0], a0);
            a1 = fmaf(s_h2[(t + 1) * Hc + tid], s_w[t + 1], a1);
            a2 = fmaf(s_h2[(t + 2) * Hc + tid], s_w[t + 2], a2);
            a3 = fmaf(s_h2[(t + 3) * Hc + tid], s_w[t + 3], a3);
        }
        s_nf[tid] = (a0 + a1) + (a2 + a3);
    }
    __syncthreads();

    // ---- GRU input gates gi = W_ih @ nf + b_ih ----
    for (int j = tid; j < 3 * Hc; j += 128) {
        const float4* row = (const float4*)(W_ih + j * Hc);
        const float4* nf4 = (const float4*)s_nf;
        float a0 = 0.f, a1 = 0.f, a2 = 0.f, a3 = 0.f;
        #pragma unroll
        for (int q = 0; q < 16; q++) {
            float4 w4 = row[q];
            float4 v4 = nf4[q];
            a0 = fmaf(w4.x, v4.x, a0);
            a1 = fmaf(w4.y, v4.y, a1);
            a2 = fmaf(w4.z, v4.z, a2);
            a3 = fmaf(w4.w, v4.w, a3);
        }
        s_gi[j] = b_ih[j] + ((a0 + a1) + (a2 + a3));
    }
    __syncthreads();

    // ---- ODE setup: weight columns in registers, state in registers ----
    float wo1[Hc], wo2[Hc];
    float bo1 = 0.f, bo2 = 0.f, yv = 0.f;
    if (tid < Hc) {
        #pragma unroll
        for (int k = 0; k < Hc; k++) {
            wo1[k] = W_o1[k * Hc + tid];
            wo2[k] = W_o2[k * Hc + tid];
        }
        bo1 = b_o1[tid]; bo2 = b_o2[tid];

        float r = fsigm(s_gi[tid]          + b_hh[tid]);
        float z = fsigm(s_gi[Hc + tid]     + b_hh[Hc + tid]);
        float n = ftanh(s_gi[2 * Hc + tid] + r * b_hh[2 * Hc + tid]);
        yv = (1.f - z) * n;
        s_in[tid] = yv;
        s_traj[0][tid] = yv;
    }
    __syncthreads();

    // ---- ODE: RK4 (3/8 rule), 23 steps. Only warps 0-1; named barrier. ----
    const float dt    = 24.0f / 23.0f;
    const float third = 1.0f / 3.0f;

    if (tid < Hc) {
        for (int s = 1; s < TFc; s++) {
            float u, k1, k2, k3, k4;

            u = ftanh(mm64(s_in, wo1, bo1)); s_u[tid] = u; ODEBAR();
            k1 = ftanh(mm64(s_u, wo2, bo2));
            s_in[tid] = fmaf(dt * third, k1, yv); ODEBAR();

            u = ftanh(mm64(s_in, wo1, bo1)); s_u[tid] = u; ODEBAR();
            k2 = ftanh(mm64(s_u, wo2, bo2));
            s_in[tid] = yv + dt * (k2 - third * k1); ODEBAR();

            u = ftanh(mm64(s_in, wo1, bo1)); s_u[tid] = u; ODEBAR();
            k3 = ftanh(mm64(s_u, wo2, bo2));
            s_in[tid] = yv + dt * (k1 - k2 + k3); ODEBAR();

            u = ftanh(mm64(s_in, wo1, bo1)); s_u[tid] = u; ODEBAR();
            k4 = ftanh(mm64(s_u, wo2, bo2));
            yv = yv + dt * 0.125f * (k1 + 3.f * (k2 + k3) + k4);
            s_in[tid] = yv; s_traj[s][tid] = yv; ODEBAR();
        }
    }
    __syncthreads();

    // ---- predictions: pred[tf] = traj[tf] . W_out + b_out ----
    {
        int w = tid >> 5, lane = tid & 31;
        for (int tf = w; tf < TFc; tf += 4) {
            float v = s_traj[tf][lane] * s_wout[lane]
                    + s_traj[tf][lane + 32] * s_wout[lane + 32];
            #pragma unroll
            for (int off = 16; off; off >>= 1) v += __shfl_xor_sync(0xffffffffu, v, off);
            if (lane == 0) s_pred[tf] = v + bout;
        }
    }
    __syncthreads();

    // ---- output: out[b][n][tf] = pred[tf] (node-constant) ----
    float* ob = out + b * (Nc * TFc);
    for (int i = tid; i < Nc * TFc; i += 128)
        ob[i] = s_pred[i % TFc];
}

extern "C" void kernel_launch(void* const* d_in, const int* in_sizes, int n_in,
                              void* d_out, int out_size)
{
    const float* x     = (const float*)d_in[0];
    const float* W_s1  = (const float*)d_in[1];
    const float* b_s1  = (const float*)d_in[2];
    const float* W_s2  = (const float*)d_in[3];
    const float* b_s2  = (const float*)d_in[4];
    const float* Wa1   = (const float*)d_in[5];
    const float* ba1   = (const float*)d_in[6];
    const float* Wa2   = (const float*)d_in[7];
    const float* ba2   = (const float*)d_in[8];
    const float* W_ih  = (const float*)d_in[9];
    const float* b_ih  = (const float*)d_in[11];
    const float* b_hh  = (const float*)d_in[12];
    const float* W_o1  = (const float*)d_in[13];
    const float* b_o1  = (const float*)d_in[14];
    const float* W_o2  = (const float*)d_in[15];
    const float* b_o2  = (const float*)d_in[16];
    const float* W_out = (const float*)d_in[17];
    const float* b_out = (const float*)d_in[18];

    const int dyn_bytes = 2 * Tc * Hc * (int)sizeof(float);  // 48KB dynamic

    // Static (~10KB) + dynamic (48KB) exceeds the 48KB default cap -> opt in.
    // cudaFuncSetAttribute is not a stream-ordered API, so it is safe during
    // graph capture; called unconditionally (idempotent, deterministic).
    cudaFuncSetAttribute(gde_kernel,
                         cudaFuncAttributeMaxDynamicSharedMemorySize, dyn_bytes);

    gde_kernel<<<Bc, 128, dyn_bytes>>>(x, W_s1, b_s1, W_s2, b_s2,
                                       Wa1, ba1, Wa2, ba2,
                                       W_ih, b_ih, b_hh,
                                       W_o1, b_o1, W_o2, b_o2,
                                       W_out, b_out, (float*)d_out);
}

// round 4
// speedup vs baseline: 2.3554x; 1.0847x over previous
#include <cuda_runtime.h>

#define Bc  32
#define Nc  128
#define Tc  96
#define Hc  64
#define TFc 24
#define TSLICE 24          // t-values per kernel-A block
#define NSL  4             // number of t-slices

// Global scratch (static device allocations are allowed)
__device__ float g_h2[Bc * Tc * Hc];    // 786 KB
__device__ float g_att[Bc * Tc];

// Overflow-safe fast tanh: tanh(x) = sign(x)*(1-e^{-2|x|})/(1+e^{-2|x|})
__device__ __forceinline__ float ftanh(float x) {
    float ax = fabsf(x);
    float e  = __expf(-2.0f * ax);
    float t  = __fdividef(1.0f - e, 1.0f + e);
    return copysignf(t, x);
}
__device__ __forceinline__ float fsigm(float x) {
    return __fdividef(1.0f, 1.0f + __expf(-x));
}

// 64-dot: shared vector (float4 broadcast) vs register column, 4 accumulators.
__device__ __forceinline__ float mm64(const float* v, const float* w, float bias) {
    const float4* v4 = (const float4*)v;
    float a0 = 0.f, a1 = 0.f, a2 = 0.f, a3 = 0.f;
    #pragma unroll
    for (int q = 0; q < 16; q++) {
        float4 xv = v4[q];
        a0 = fmaf(xv.x, w[4 * q + 0], a0);
        a1 = fmaf(xv.y, w[4 * q + 1], a1);
        a2 = fmaf(xv.z, w[4 * q + 2], a2);
        a3 = fmaf(xv.w, w[4 * q + 3], a3);
    }
    return bias + ((a0 + a1) + (a2 + a3));
}

// ===================== Kernel A: spatial encoder + attention logits =========
// grid: (NSL, Bc), block: 128. Each block handles 24 t-values of one batch.
__global__ __launch_bounds__(128, 1)
void front_kernel(const float* __restrict__ x,
                  const float* __restrict__ W_s1, const float* __restrict__ b_s1,
                  const float* __restrict__ W_s2, const float* __restrict__ b_s2,
                  const float* __restrict__ Wa1,  const float* __restrict__ ba1,
                  const float* __restrict__ Wa2,  const float* __restrict__ ba2)
{
    __shared__ __align__(16) float s_mx[TSLICE];
    __shared__ __align__(16) float s_h1[TSLICE][Hc];
    __shared__ __align__(16) float s_h2[TSLICE][Hc];
    __shared__ float s_att[TSLICE];

    const int tid = threadIdx.x;
    const int b   = blockIdx.y;
    const int t0  = blockIdx.x * TSLICE;
    const float* xb = x + b * (Nc * Tc);

    // ---- mean over nodes: 4 threads per t (32 nodes each), shfl combine ----
    if (tid < 96) {
        int t = tid >> 2, q = tid & 3;
        const float* p = xb + t0 + t;
        float s = 0.f;
        #pragma unroll 8
        for (int n = q * 32; n < q * 32 + 32; n++) s += p[n * Tc];
        s += __shfl_xor_sync(0xffffffffu, s, 1);
        s += __shfl_xor_sync(0xffffffffu, s, 2);
        if (q == 0) s_mx[t] = s * (1.0f / Nc);
    }
    __syncthreads();

    // ---- h1[t][k] = relu(mx*Ws1 + bs1) ----
    {
        int k = tid & 63;
        float wk = W_s1[k], bk = b_s1[k];
        for (int t = tid >> 6; t < TSLICE; t += 2)
            s_h1[t][k] = fmaxf(fmaf(s_mx[t], wk, bk), 0.f);
    }
    __syncthreads();

    // ---- h2[t][h] = relu(h1[t] . Ws2[:,h] + bs2[h]) -> shared + global ----
    {
        int h = tid & 63;
        float wcol[Hc];
        #pragma unroll
        for (int k = 0; k < Hc; k++) wcol[k] = W_s2[k * Hc + h];
        float bias = b_s2[h];
        for (int t = tid >> 6; t < TSLICE; t += 2) {
            float a = fmaxf(mm64(s_h1[t], wcol, bias), 0.f);
            s_h2[t][h] = a;
            g_h2[(b * Tc + t0 + t) * Hc + h] = a;
        }
    }
    if (tid < TSLICE) s_att[tid] = 0.f;
    __syncthreads();

    // ---- att[t] = sum_h tanh(h2[t].Wa1[:,h] + ba1[h]) * Wa2[h] ----
    {
        int h = tid & 63;
        float wcol[Hc];
        #pragma unroll
        for (int k = 0; k < Hc; k++) wcol[k] = Wa1[k * Hc + h];
        float bias = ba1[h];
        float wa2  = Wa2[h];
        for (int t = tid >> 6; t < TSLICE; t += 2) {
            float v = ftanh(mm64(s_h2[t], wcol, bias)) * wa2;
            #pragma unroll
            for (int off = 16; off; off >>= 1) v += __shfl_xor_sync(0xffffffffu, v, off);
            if ((tid & 31) == 0) atomicAdd(&s_att[t], v);
        }
    }
    __syncthreads();

    if (tid < TSLICE) g_att[b * Tc + t0 + tid] = s_att[tid] + ba2[0];
}

// ===================== Kernel B: softmax + GRU + ODE + output ===============
__global__ __launch_bounds__(128, 1)
void ode_kernel(const float* __restrict__ W_ih, const float* __restrict__ b_ih,
                const float* __restrict__ b_hh,
                const float* __restrict__ W_o1, const float* __restrict__ b_o1,
                const float* __restrict__ W_o2, const float* __restrict__ b_o2,
                const float* __restrict__ W_out,const float* __restrict__ b_out,
                float* __restrict__ out)
{
    __shared__ __align__(16) float s_w[Tc];
    __shared__ __align__(16) float s_nf[Hc];
    __shared__ __align__(16) float s_gi[3 * Hc];
    __shared__ __align__(16) float s_in[Hc], s_u[Hc];
    __shared__ __align__(16) float s_traj[TFc][Hc];
    __shared__ __align__(16) float s_wout[Hc];
    __shared__ float s_pred[TFc];

    const int tid = threadIdx.x;
    const int b   = blockIdx.x;
    const float bout = b_out[0];

    if (tid < Hc) s_wout[tid] = W_out[tid];

    // ---- softmax over t (warp 0; att from global) ----
    if (tid < 32) {
        const float* ab = g_att + b * Tc;
        float a0 = ab[tid], a1 = ab[tid + 32], a2 = ab[tid + 64];
        float m = fmaxf(a0, fmaxf(a1, a2));
        #pragma unroll
        for (int off = 16; off; off >>= 1) m = fmaxf(m, __shfl_xor_sync(0xffffffffu, m, off));
        float e0 = __expf(a0 - m), e1 = __expf(a1 - m), e2 = __expf(a2 - m);
        float s = e0 + e1 + e2;
        #pragma unroll
        for (int off = 16; off; off >>= 1) s += __shfl_xor_sync(0xffffffffu, s, off);
        float inv = __fdividef(1.f, s);
        s_w[tid] = e0 * inv; s_w[tid + 32] = e1 * inv; s_w[tid + 64] = e2 * inv;
    }
    __syncthreads();

    // ---- nf[h] = sum_t h2[t][h] * w[t]  (h2 from global scratch, L2-hot) ----
    if (tid < Hc) {
        const float* hb = g_h2 + b * Tc * Hc + tid;
        float a0 = 0.f, a1 = 0.f, a2 = 0.f, a3 = 0.f;
        #pragma unroll 4
        for (int t = 0; t < Tc; t += 4) {
            a0 = fmaf(hb[(t + 0) * Hc], s_w[t + 0], a0);
            a1 = fmaf(hb[(t + 1) * Hc], s_w[t + 1], a1);
            a2 = fmaf(hb[(t + 2) * Hc], s_w[t + 2], a2);
            a3 = fmaf(hb[(t + 3) * Hc], s_w[t + 3], a3);
        }
        s_nf[tid] = (a0 + a1) + (a2 + a3);
    }
    __syncthreads();

    // ---- GRU input gates ----
    for (int j = tid; j < 3 * Hc; j += 128) {
        const float4* row = (const float4*)(W_ih + j * Hc);
        const float4* nf4 = (const float4*)s_nf;
        float a0 = 0.f, a1 = 0.f, a2 = 0.f, a3 = 0.f;
        #pragma unroll
        for (int q = 0; q < 16; q++) {
            float4 w4 = row[q];
            float4 v4 = nf4[q];
            a0 = fmaf(w4.x, v4.x, a0);
            a1 = fmaf(w4.y, v4.y, a1);
            a2 = fmaf(w4.z, v4.z, a2);
            a3 = fmaf(w4.w, v4.w, a3);
        }
        s_gi[j] = b_ih[j] + ((a0 + a1) + (a2 + a3));
    }
    __syncthreads();

    // ---- ODE setup: 2-way K-split. Thread pair (2h, 2h+1) owns output h. ----
    const int hh   = tid >> 1;     // output index 0..63
    const int half = tid & 1;      // K-half
    float w1s[32], w2s[32];
    #pragma unroll
    for (int k = 0; k < 32; k++) {
        w1s[k] = W_o1[(half * 32 + k) * Hc + hh];
        w2s[k] = W_o2[(half * 32 + k) * Hc + hh];
    }
    const float bo1 = b_o1[hh], bo2 = b_o2[hh];

    // GRU nonlinearity + initial state (both halves compute identical yv)
    float yv;
    {
        float r = fsigm(s_gi[hh]          + b_hh[hh]);
        float z = fsigm(s_gi[Hc + hh]     + b_hh[Hc + hh]);
        float n = ftanh(s_gi[2 * Hc + hh] + r * b_hh[2 * Hc + hh]);
        yv = (1.f - z) * n;
        if (!half) { s_in[hh] = yv; s_traj[0][hh] = yv; }
    }
    __syncthreads();

    // 32-MAC half-dot against this thread's K-half, then pair-combine.
    #define HDOT(VEC, W)                                                        \
        ({ const float4* v4 = (const float4*)((VEC) + half * 32);               \
           float a0 = 0.f, a1 = 0.f, a2 = 0.f, a3 = 0.f;                        \
           _Pragma("unroll")                                                    \
           for (int q = 0; q < 8; q++) {                                        \
               float4 xv = v4[q];                                               \
               a0 = fmaf(xv.x, W[4 * q + 0], a0);                               \
               a1 = fmaf(xv.y, W[4 * q + 1], a1);                               \
               a2 = fmaf(xv.z, W[4 * q + 2], a2);                               \
               a3 = fmaf(xv.w, W[4 * q + 3], a3);                               \
           }                                                                    \
           float p = (a0 + a1) + (a2 + a3);                                     \
           p + __shfl_xor_sync(0xffffffffu, p, 1); })

    const float dt    = 24.0f / 23.0f;
    const float third = 1.0f / 3.0f;

    for (int s = 1; s < TFc; s++) {
        float u, k1, k2, k3, k4;

        u = ftanh(HDOT(s_in, w1s) + bo1);
        if (!half) s_u[hh] = u;
        __syncthreads();
        k1 = ftanh(HDOT(s_u, w2s) + bo2);
        if (!half) s_in[hh] = fmaf(dt * third, k1, yv);
        __syncthreads();

        u = ftanh(HDOT(s_in, w1s) + bo1);
        if (!half) s_u[hh] = u;
        __syncthreads();
        k2 = ftanh(HDOT(s_u, w2s) + bo2);
        if (!half) s_in[hh] = yv + dt * (k2 - third * k1);
        __syncthreads();

        u = ftanh(HDOT(s_in, w1s) + bo1);
        if (!half) s_u[hh] = u;
        __syncthreads();
        k3 = ftanh(HDOT(s_u, w2s) + bo2);
        if (!half) s_in[hh] = yv + dt * (k1 - k2 + k3);
        __syncthreads();

        u = ftanh(HDOT(s_in, w1s) + bo1);
        if (!half) s_u[hh] = u;
        __syncthreads();
        k4 = ftanh(HDOT(s_u, w2s) + bo2);
        yv = yv + dt * 0.125f * (k1 + 3.f * (k2 + k3) + k4);
        if (!half) { s_in[hh] = yv; s_traj[s][hh] = yv; }
        __syncthreads();
    }

    // ---- predictions: pred[tf] = traj[tf] . W_out + b_out ----
    {
        int w = tid >> 5, lane = tid & 31;
        for (int tf = w; tf < TFc; tf += 4) {
            float v = s_traj[tf][lane] * s_wout[lane]
                    + s_traj[tf][lane + 32] * s_wout[lane + 32];
            #pragma unroll
            for (int off = 16; off; off >>= 1) v += __shfl_xor_sync(0xffffffffu, v, off);
            if (lane == 0) s_pred[tf] = v + bout;
        }
    }
    __syncthreads();

    // ---- output: out[b][n][tf] = pred[tf] (node-constant) ----
    float* ob = out + b * (Nc * TFc);
    for (int i = tid; i < Nc * TFc; i += 128)
        ob[i] = s_pred[i % TFc];
}

extern "C" void kernel_launch(void* const* d_in, const int* in_sizes, int n_in,
                              void* d_out, int out_size)
{
    const float* x     = (const float*)d_in[0];
    const float* W_s1  = (const float*)d_in[1];
    const float* b_s1  = (const float*)d_in[2];
    const float* W_s2  = (const float*)d_in[3];
    const float* b_s2  = (const float*)d_in[4];
    const float* Wa1   = (const float*)d_in[5];
    const float* ba1   = (const float*)d_in[6];
    const float* Wa2   = (const float*)d_in[7];
    const float* ba2   = (const float*)d_in[8];
    const float* W_ih  = (const float*)d_in[9];
    const float* b_ih  = (const float*)d_in[11];
    const float* b_hh  = (const float*)d_in[12];
    const float* W_o1  = (const float*)d_in[13];
    const float* b_o1  = (const float*)d_in[14];
    const float* W_o2  = (const float*)d_in[15];
    const float* b_o2  = (const float*)d_in[16];
    const float* W_out = (const float*)d_in[17];
    const float* b_out = (const float*)d_in[18];

    dim3 gridA(NSL, Bc);
    front_kernel<<<gridA, 128>>>(x, W_s1, b_s1, W_s2, b_s2,
                                 Wa1, ba1, Wa2, ba2);
    ode_kernel<<<Bc, 128>>>(W_ih, b_ih, b_hh,
                            W_o1, b_o1, W_o2, b_o2,
                            W_out, b_out, (float*)d_out);
}

// round 5
// speedup vs baseline: 2.3675x; 1.0052x over previous
#include <cuda_runtime.h>

#define Bc  32
#define Nc  128
#define Tc  96
#define Hc  64
#define TFc 24

// Cross-kernel scratch: GRU hidden state per (batch, h).
__device__ float g_hid[Bc * Hc];

// Overflow-safe fast tanh: 1 - 2/(e^{2x}+1).  x->+inf: e=inf -> 1; x->-inf: e=0 -> -1.
__device__ __forceinline__ float ftanh(float x) {
    float e = __expf(2.0f * x);
    return 1.0f - __fdividef(2.0f, e + 1.0f);
}
__device__ __forceinline__ float fsigm(float x) {
    return __fdividef(1.0f, 1.0f + __expf(-x));
}

__device__ __forceinline__ unsigned long long pack2(float lo, float hi) {
    unsigned long long r;
    asm("mov.b64 %0, {%1, %2};" : "=l"(r) : "f"(lo), "f"(hi));
    return r;
}

// 64-element dot: v in shared (16B aligned), w = 32 packed f32x2 pairs in regs.
// 16 LDS.128-equivalent loads + 32 FFMA2 (packed), 4 accumulators.
__device__ __forceinline__ float dot64(const float* v, const unsigned long long* w) {
    const ulonglong2* v2 = (const ulonglong2*)v;
    unsigned long long a0 = 0ULL, a1 = 0ULL, a2 = 0ULL, a3 = 0ULL;
    #pragma unroll
    for (int q = 0; q < 16; q += 2) {
        ulonglong2 va = v2[q];
        ulonglong2 vb = v2[q + 1];
        asm("fma.rn.f32x2 %0, %1, %2, %0;" : "+l"(a0) : "l"(va.x), "l"(w[2*q + 0]));
        asm("fma.rn.f32x2 %0, %1, %2, %0;" : "+l"(a1) : "l"(va.y), "l"(w[2*q + 1]));
        asm("fma.rn.f32x2 %0, %1, %2, %0;" : "+l"(a2) : "l"(vb.x), "l"(w[2*q + 2]));
        asm("fma.rn.f32x2 %0, %1, %2, %0;" : "+l"(a3) : "l"(vb.y), "l"(w[2*q + 3]));
    }
    float l0, h0, l1, h1, l2, h2, l3, h3;
    asm("mov.b64 {%0,%1}, %2;" : "=f"(l0), "=f"(h0) : "l"(a0));
    asm("mov.b64 {%0,%1}, %2;" : "=f"(l1), "=f"(h1) : "l"(a1));
    asm("mov.b64 {%0,%1}, %2;" : "=f"(l2), "=f"(h2) : "l"(a2));
    asm("mov.b64 {%0,%1}, %2;" : "=f"(l3), "=f"(h3) : "l"(a3));
    return ((l0 + h0) + (l1 + h1)) + ((l2 + h2) + (l3 + h3));
}

// ============ Kernel A: spatial encoder + attention + GRU -> g_hid ==========
// grid: Bc, block: 512. One block per batch.
__global__ __launch_bounds__(512, 1)
void front_kernel(const float* __restrict__ x,
                  const float* __restrict__ W_s1, const float* __restrict__ b_s1,
                  const float* __restrict__ W_s2, const float* __restrict__ b_s2,
                  const float* __restrict__ Wa1,  const float* __restrict__ ba1,
                  const float* __restrict__ Wa2,
                  const float* __restrict__ W_ih, const float* __restrict__ b_ih,
                  const float* __restrict__ b_hh)
{
    __shared__ __align__(16) float s_h1[48][Hc];     // 12 KB (chunked over t)
    __shared__ __align__(16) float s_h2[Tc][Hc];     // 24 KB
    __shared__ __align__(16) float s_mx[Tc];
    __shared__ __align__(16) float s_att[Tc], s_w[Tc];
    __shared__ __align__(16) float s_nf[Hc];
    __shared__ __align__(16) float s_gi[3 * Hc];

    const int tid = threadIdx.x;
    const int b   = blockIdx.x;
    const float* xb = x + b * (Nc * Tc);

    // ---- mean over nodes: 4 threads per t (32 nodes each) ----
    if (tid < 384) {
        int t = tid >> 2, q = tid & 3;
        const float* p = xb + t;
        float s = 0.f;
        #pragma unroll 8
        for (int n = q * 32; n < q * 32 + 32; n++) s += p[n * Tc];
        s += __shfl_xor_sync(0xffffffffu, s, 1);
        s += __shfl_xor_sync(0xffffffffu, s, 2);
        if (q == 0) s_mx[t] = s * (1.0f / Nc);
    }
    if (tid < Tc) s_att[tid] = 0.f;
    __syncthreads();

    const int h  = tid & 63;
    const int tg = tid >> 6;   // 0..7

    // ---- W_s2 column packed in regs (coalesced per-pair loads, L1/L2 hot) ----
    {
        unsigned long long wp[32];
        #pragma unroll
        for (int j = 0; j < 32; j++)
            wp[j] = pack2(W_s2[(2 * j) * Hc + h], W_s2[(2 * j + 1) * Hc + h]);
        float bs2h = b_s2[h];

        for (int c = 0; c < 2; c++) {
            // h1 chunk: 48*64 items, 6 per thread
            #pragma unroll
            for (int i = 0; i < 6; i++) {
                int item = tid + 512 * i;
                int tl = item >> 6, k = item & 63;
                s_h1[tl][k] = fmaxf(fmaf(s_mx[c * 48 + tl], W_s1[k], b_s1[k]), 0.f);
            }
            __syncthreads();
            // h2 chunk: thread (h, tg) covers t = tg + 8i
            #pragma unroll
            for (int i = 0; i < 6; i++) {
                int tl = tg + 8 * i;
                float a = dot64(s_h1[tl], wp) + bs2h;
                s_h2[c * 48 + tl][h] = fmaxf(a, 0.f);
            }
            __syncthreads();
        }
    }

    // ---- attention logits (ba2 dropped: softmax shift-invariant) ----
    {
        unsigned long long wa[32];
        #pragma unroll
        for (int j = 0; j < 32; j++)
            wa[j] = pack2(Wa1[(2 * j) * Hc + h], Wa1[(2 * j + 1) * Hc + h]);
        float ba1h = ba1[h];
        float wa2h = Wa2[h];
        #pragma unroll
        for (int i = 0; i < 12; i++) {
            int t = tg + 8 * i;
            float v = ftanh(dot64(s_h2[t], wa) + ba1h) * wa2h;
            #pragma unroll
            for (int off = 16; off; off >>= 1) v += __shfl_xor_sync(0xffffffffu, v, off);
            if ((tid & 31) == 0) atomicAdd(&s_att[t], v);
        }
    }
    __syncthreads();

    // ---- softmax over t (warp 0) ----
    if (tid < 32) {
        float a0 = s_att[tid], a1 = s_att[tid + 32], a2 = s_att[tid + 64];
        float m = fmaxf(a0, fmaxf(a1, a2));
        #pragma unroll
        for (int off = 16; off; off >>= 1) m = fmaxf(m, __shfl_xor_sync(0xffffffffu, m, off));
        float e0 = __expf(a0 - m), e1 = __expf(a1 - m), e2 = __expf(a2 - m);
        float s = e0 + e1 + e2;
        #pragma unroll
        for (int off = 16; off; off >>= 1) s += __shfl_xor_sync(0xffffffffu, s, off);
        float inv = __fdividef(1.f, s);
        s_w[tid] = e0 * inv; s_w[tid + 32] = e1 * inv; s_w[tid + 64] = e2 * inv;
    }
    __syncthreads();

    // ---- nf[h] = sum_t h2[t][h] * w[t] ----
    if (tid < Hc) {
        float a0 = 0.f, a1 = 0.f, a2 = 0.f, a3 = 0.f;
        #pragma unroll 4
        for (int t = 0; t < Tc; t += 4) {
            a0 = fmaf(s_h2[t + 0][tid], s_w[t + 0], a0);
            a1 = fmaf(s_h2[t + 1][tid], s_w[t + 1], a1);
            a2 = fmaf(s_h2[t + 2][tid], s_w[t + 2], a2);
            a3 = fmaf(s_h2[t + 3][tid], s_w[t + 3], a3);
        }
        s_nf[tid] = (a0 + a1) + (a2 + a3);
    }
    __syncthreads();

    // ---- GRU gemv: one warp per row group, lane k-split (coalesced) ----
    {
        int w = tid >> 5, lane = tid & 31;   // 16 warps
        for (int j = w; j < 3 * Hc; j += 16) {
            float acc = W_ih[j * Hc + lane]      * s_nf[lane]
                      + W_ih[j * Hc + 32 + lane] * s_nf[32 + lane];
            #pragma unroll
            for (int off = 16; off; off >>= 1) acc += __shfl_xor_sync(0xffffffffu, acc, off);
            if (lane == 0) s_gi[j] = b_ih[j] + acc;
        }
    }
    __syncthreads();

    // ---- gates -> hidden -> global ----
    if (tid < Hc) {
        float r = fsigm(s_gi[tid]          + b_hh[tid]);
        float z = fsigm(s_gi[Hc + tid]     + b_hh[Hc + tid]);
        float n = ftanh(s_gi[2 * Hc + tid] + r * b_hh[2 * Hc + tid]);
        g_hid[b * Hc + tid] = (1.f - z) * n;
    }
}

// ============ Kernel B: ODE (RK4 3/8) + output ==============================
// grid: Bc, block: 64. Thread h owns output component h; weights packed f32x2.
__global__ __launch_bounds__(64, 1)
void ode_kernel(const float* __restrict__ W_o1, const float* __restrict__ b_o1,
                const float* __restrict__ W_o2, const float* __restrict__ b_o2,
                const float* __restrict__ W_out,const float* __restrict__ b_out,
                float* __restrict__ out)
{
    __shared__ __align__(16) float s_in[Hc], s_u[Hc];
    __shared__ __align__(16) float s_traj[TFc][Hc];
    __shared__ __align__(16) float s_wout[Hc];
    __shared__ float s_pred[TFc];

    const int h = threadIdx.x;
    const int b = blockIdx.x;
    const float bout = b_out[0];

    // pack weight columns: w1p[j] pairs rows (2j, 2j+1) of column h
    unsigned long long w1p[32], w2p[32];
    #pragma unroll
    for (int j = 0; j < 32; j++) {
        w1p[j] = pack2(W_o1[(2 * j) * Hc + h], W_o1[(2 * j + 1) * Hc + h]);
        w2p[j] = pack2(W_o2[(2 * j) * Hc + h], W_o2[(2 * j + 1) * Hc + h]);
    }
    const float bo1 = b_o1[h], bo2 = b_o2[h];
    s_wout[h] = W_out[h];

    float yv = g_hid[b * Hc + h];
    s_in[h] = yv;
    s_traj[0][h] = yv;
    __syncthreads();

    const float dt    = 24.0f / 23.0f;
    const float third = 1.0f / 3.0f;

    for (int s = 1; s < TFc; s++) {
        float u, k1, k2, k3, k4;

        u = ftanh(dot64(s_in, w1p) + bo1); s_u[h] = u; __syncthreads();
        k1 = ftanh(dot64(s_u, w2p) + bo2);
        s_in[h] = fmaf(dt * third, k1, yv); __syncthreads();

        u = ftanh(dot64(s_in, w1p) + bo1); s_u[h] = u; __syncthreads();
        k2 = ftanh(dot64(s_u, w2p) + bo2);
        s_in[h] = yv + dt * (k2 - third * k1); __syncthreads();

        u = ftanh(dot64(s_in, w1p) + bo1); s_u[h] = u; __syncthreads();
        k3 = ftanh(dot64(s_u, w2p) + bo2);
        s_in[h] = yv + dt * (k1 - k2 + k3); __syncthreads();

        u = ftanh(dot64(s_in, w1p) + bo1); s_u[h] = u; __syncthreads();
        k4 = ftanh(dot64(s_u, w2p) + bo2);
        yv = yv + dt * 0.125f * (k1 + 3.f * (k2 + k3) + k4);
        s_in[h] = yv; s_traj[s][h] = yv; __syncthreads();
    }

    // ---- predictions: pred[tf] = traj[tf] . W_out + b_out (2 warps) ----
    {
        int w = h >> 5, lane = h & 31;
        for (int tf = w; tf < TFc; tf += 2) {
            float v = s_traj[tf][lane] * s_wout[lane]
                    + s_traj[tf][lane + 32] * s_wout[lane + 32];
            #pragma unroll
            for (int off = 16; off; off >>= 1) v += __shfl_xor_sync(0xffffffffu, v, off);
            if (lane == 0) s_pred[tf] = v + bout;
        }
    }
    __syncthreads();

    // ---- out[b][n][tf] = pred[tf] (node-constant) ----
    float* ob = out + b * (Nc * TFc);
    for (int i = h; i < Nc * TFc; i += 64)
        ob[i] = s_pred[i % TFc];
}

extern "C" void kernel_launch(void* const* d_in, const int* in_sizes, int n_in,
                              void* d_out, int out_size)
{
    const float* x     = (const float*)d_in[0];
    const float* W_s1  = (const float*)d_in[1];
    const float* b_s1  = (const float*)d_in[2];
    const float* W_s2  = (const float*)d_in[3];
    const float* b_s2  = (const float*)d_in[4];
    const float* Wa1   = (const float*)d_in[5];
    const float* ba1   = (const float*)d_in[6];
    const float* Wa2   = (const float*)d_in[7];
    const float* W_ih  = (const float*)d_in[9];
    const float* b_ih  = (const float*)d_in[11];
    const float* b_hh  = (const float*)d_in[12];
    const float* W_o1  = (const float*)d_in[13];
    const float* b_o1  = (const float*)d_in[14];
    const float* W_o2  = (const float*)d_in[15];
    const float* b_o2  = (const float*)d_in[16];
    const float* W_out = (const float*)d_in[17];
    const float* b_out = (const float*)d_in[18];

    front_kernel<<<Bc, 512>>>(x, W_s1, b_s1, W_s2, b_s2,
                              Wa1, ba1, Wa2,
                              W_ih, b_ih, b_hh);
    ode_kernel<<<Bc, 64>>>(W_o1, b_o1, W_o2, b_o2,
                           W_out, b_out, (float*)d_out);
}

// round 8
// speedup vs baseline: 2.8333x; 1.1968x over previous
#include <cuda_runtime.h>

#define Bc  32
#define Nc  128
#define Tc  96
#define Hc  64
#define TFc 24
#define TSLICE 24
#define NSL  4

// Cross-kernel scratch
__device__ float g_h2[Bc * Tc * Hc];    // 768 KB (L2-resident)
__device__ float g_att[Bc * Tc];

// Overflow-safe fast tanh: 1 - 2/(e^{2x}+1)
__device__ __forceinline__ float ftanh(float x) {
    float e = __expf(2.0f * x);
    return 1.0f - __fdividef(2.0f, e + 1.0f);
}
__device__ __forceinline__ float fsigm(float x) {
    return __fdividef(1.0f, 1.0f + __expf(-x));
}

__device__ __forceinline__ unsigned long long pack2(float lo, float hi) {
    unsigned long long r;
    asm("mov.b64 %0, {%1, %2};" : "=l"(r) : "f"(lo), "f"(hi));
    return r;
}

// 64-dot: v in shared (16B aligned) vs 32 packed f32x2 pairs in regs.
__device__ __forceinline__ float dot64p(const float* v, const unsigned long long* w) {
    const ulonglong2* v2 = (const ulonglong2*)v;
    unsigned long long a0 = 0ULL, a1 = 0ULL, a2 = 0ULL, a3 = 0ULL;
    #pragma unroll
    for (int q = 0; q < 16; q += 2) {
        ulonglong2 va = v2[q];
        ulonglong2 vb = v2[q + 1];
        asm("fma.rn.f32x2 %0, %1, %2, %0;" : "+l"(a0) : "l"(va.x), "l"(w[2*q + 0]));
        asm("fma.rn.f32x2 %0, %1, %2, %0;" : "+l"(a1) : "l"(va.y), "l"(w[2*q + 1]));
        asm("fma.rn.f32x2 %0, %1, %2, %0;" : "+l"(a2) : "l"(vb.x), "l"(w[2*q + 2]));
        asm("fma.rn.f32x2 %0, %1, %2, %0;" : "+l"(a3) : "l"(vb.y), "l"(w[2*q + 3]));
    }
    float l0, h0, l1, h1, l2, h2, l3, h3;
    asm("mov.b64 {%0,%1}, %2;" : "=f"(l0), "=f"(h0) : "l"(a0));
    asm("mov.b64 {%0,%1}, %2;" : "=f"(l1), "=f"(h1) : "l"(a1));
    asm("mov.b64 {%0,%1}, %2;" : "=f"(l2), "=f"(h2) : "l"(a2));
    asm("mov.b64 {%0,%1}, %2;" : "=f"(l3), "=f"(h3) : "l"(a3));
    return ((l0 + h0) + (l1 + h1)) + ((l2 + h2) + (l3 + h3));
}

// 64-dot: shared vector vs 64 scalar float regs (front kernel; lighter pressure).
__device__ __forceinline__ float mm64(const float* v, const float* w, float bias) {
    const float4* v4 = (const float4*)v;
    float a0 = 0.f, a1 = 0.f, a2 = 0.f, a3 = 0.f;
    #pragma unroll
    for (int q = 0; q < 16; q++) {
        float4 xv = v4[q];
        a0 = fmaf(xv.x, w[4 * q + 0], a0);
        a1 = fmaf(xv.y, w[4 * q + 1], a1);
        a2 = fmaf(xv.z, w[4 * q + 2], a2);
        a3 = fmaf(xv.w, w[4 * q + 3], a3);
    }
    return bias + ((a0 + a1) + (a2 + a3));
}

#define ODEBAR() asm volatile("bar.sync 1, 64;" ::: "memory")

// ===================== Kernel A: spatial encoder + attention logits =========
// grid: (NSL, Bc), block: 128. Each block: 24 t-values of one batch. (R4-proven)
__global__ __launch_bounds__(128, 1)
void front_kernel(const float* __restrict__ x,
                  const float* __restrict__ W_s1, const float* __restrict__ b_s1,
                  const float* __restrict__ W_s2, const float* __restrict__ b_s2,
                  const float* __restrict__ Wa1,  const float* __restrict__ ba1,
                  const float* __restrict__ Wa2)
{
    __shared__ __align__(16) float s_mx[TSLICE];
    __shared__ __align__(16) float s_h1[TSLICE][Hc];
    __shared__ __align__(16) float s_h2[TSLICE][Hc];
    __shared__ float s_att[TSLICE];

    const int tid = threadIdx.x;
    const int b   = blockIdx.y;
    const int t0  = blockIdx.x * TSLICE;
    const float* xb = x + b * (Nc * Tc);

    // mean over nodes: 4 threads per t
    if (tid < 96) {
        int t = tid >> 2, q = tid & 3;
        const float* p = xb + t0 + t;
        float s = 0.f;
        #pragma unroll 8
        for (int n = q * 32; n < q * 32 + 32; n++) s += p[n * Tc];
        s += __shfl_xor_sync(0xffffffffu, s, 1);
        s += __shfl_xor_sync(0xffffffffu, s, 2);
        if (q == 0) s_mx[t] = s * (1.0f / Nc);
    }
    __syncthreads();

    {
        int k = tid & 63;
        float wk = W_s1[k], bk = b_s1[k];
        for (int t = tid >> 6; t < TSLICE; t += 2)
            s_h1[t][k] = fmaxf(fmaf(s_mx[t], wk, bk), 0.f);
    }
    __syncthreads();

    {
        int h = tid & 63;
        float wcol[Hc];
        #pragma unroll
        for (int k = 0; k < Hc; k++) wcol[k] = W_s2[k * Hc + h];
        float bias = b_s2[h];
        for (int t = tid >> 6; t < TSLICE; t += 2) {
            float a = fmaxf(mm64(s_h1[t], wcol, bias), 0.f);
            s_h2[t][h] = a;
            g_h2[(b * Tc + t0 + t) * Hc + h] = a;
        }
    }
    if (tid < TSLICE) s_att[tid] = 0.f;
    __syncthreads();

    {
        int h = tid & 63;
        float wcol[Hc];
        #pragma unroll
        for (int k = 0; k < Hc; k++) wcol[k] = Wa1[k * Hc + h];
        float bias = ba1[h];
        float wa2  = Wa2[h];
        for (int t = tid >> 6; t < TSLICE; t += 2) {
            float v = ftanh(mm64(s_h2[t], wcol, bias)) * wa2;
            #pragma unroll
            for (int off = 16; off; off >>= 1) v += __shfl_xor_sync(0xffffffffu, v, off);
            if ((tid & 31) == 0) atomicAdd(&s_att[t], v);
        }
    }
    __syncthreads();

    if (tid < TSLICE) g_att[b * Tc + t0 + tid] = s_att[tid];
}

// ============ Kernel B: softmax + nf + GRU + ODE + output ===================
// grid: Bc, block: 128. ODE loop on threads <64 (named barrier 1).
__global__ __launch_bounds__(128, 1)
void ode_kernel(const float* __restrict__ W_ih, const float* __restrict__ b_ih,
                const float* __restrict__ b_hh,
                const float* __restrict__ W_o1, const float* __restrict__ b_o1,
                const float* __restrict__ W_o2, const float* __restrict__ b_o2,
                const float* __restrict__ W_out,const float* __restrict__ b_out,
                float* __restrict__ out)
{
    __shared__ __align__(16) float s_w[Tc];
    __shared__ __align__(16) float s_nf[Hc];
    __shared__ __align__(16) float s_gi[3 * Hc];
    __shared__ __align__(16) float s_in[Hc], s_u[Hc];
    __shared__ __align__(16) float s_traj[TFc][Hc];
    __shared__ __align__(16) float s_wout[Hc];
    __shared__ float s_pred[TFc];

    const int tid = threadIdx.x;
    const int b   = blockIdx.x;
    const float bout = b_out[0];

    if (tid < Hc) s_wout[tid] = W_out[tid];

    // softmax over t (warp 0)
    if (tid < 32) {
        const float* ab = g_att + b * Tc;
        float a0 = ab[tid], a1 = ab[tid + 32], a2 = ab[tid + 64];
        float m = fmaxf(a0, fmaxf(a1, a2));
        #pragma unroll
        for (int off = 16; off; off >>= 1) m = fmaxf(m, __shfl_xor_sync(0xffffffffu, m, off));
        float e0 = __expf(a0 - m), e1 = __expf(a1 - m), e2 = __expf(a2 - m);
        float s = e0 + e1 + e2;
        #pragma unroll
        for (int off = 16; off; off >>= 1) s += __shfl_xor_sync(0xffffffffu, s, off);
        float inv = __fdividef(1.f, s);
        s_w[tid] = e0 * inv; s_w[tid + 32] = e1 * inv; s_w[tid + 64] = e2 * inv;
    }
    __syncthreads();

    // nf[h] = sum_t h2[t][h] * w[t]  (two threads per h, t-split, L2-hot)
    if (tid < 128) {
        int h = tid & 63, half = tid >> 6;
        const float* hb = g_h2 + b * Tc * Hc + h + half * 48 * Hc;
        const float* wb = s_w + half * 48;
        float a0 = 0.f, a1 = 0.f, a2 = 0.f, a3 = 0.f;
        #pragma unroll 3
        for (int t = 0; t < 48; t += 4) {
            a0 = fmaf(hb[(t + 0) * Hc], wb[t + 0], a0);
            a1 = fmaf(hb[(t + 1) * Hc], wb[t + 1], a1);
            a2 = fmaf(hb[(t + 2) * Hc], wb[t + 2], a2);
            a3 = fmaf(hb[(t + 3) * Hc], wb[t + 3], a3);
        }
        float p = (a0 + a1) + (a2 + a3);
        if (half) s_nf[h] = p;            // upper half writes first
        __syncthreads();
        if (!half) s_nf[h] += p;
    }
    __syncthreads();

    // GRU gemv: row per thread (float4 row loads)
    for (int j = tid; j < 3 * Hc; j += 128) {
        const float4* row = (const float4*)(W_ih + j * Hc);
        const float4* nf4 = (const float4*)s_nf;
        float a0 = 0.f, a1 = 0.f, a2 = 0.f, a3 = 0.f;
        #pragma unroll
        for (int q = 0; q < 16; q++) {
            float4 w4 = row[q];
            float4 v4 = nf4[q];
            a0 = fmaf(w4.x, v4.x, a0);
            a1 = fmaf(w4.y, v4.y, a1);
            a2 = fmaf(w4.z, v4.z, a2);
            a3 = fmaf(w4.w, v4.w, a3);
        }
        s_gi[j] = b_ih[j] + ((a0 + a1) + (a2 + a3));
    }
    __syncthreads();

    // ODE: threads <64 only; thread h owns component h.
    if (tid < Hc) {
        const int h = tid;
        unsigned long long w1p[32], w2p[32];
        #pragma unroll
        for (int j = 0; j < 32; j++) {
            w1p[j] = pack2(W_o1[(2 * j) * Hc + h], W_o1[(2 * j + 1) * Hc + h]);
            w2p[j] = pack2(W_o2[(2 * j) * Hc + h], W_o2[(2 * j + 1) * Hc + h]);
        }
        const float bo1 = b_o1[h], bo2 = b_o2[h];

        float r = fsigm(s_gi[h]          + b_hh[h]);
        float z = fsigm(s_gi[Hc + h]     + b_hh[Hc + h]);
        float n = ftanh(s_gi[2 * Hc + h] + r * b_hh[2 * Hc + h]);
        float yv = (1.f - z) * n;
        s_in[h] = yv;
        s_traj[0][h] = yv;
        ODEBAR();

        const float dt    = 24.0f / 23.0f;
        const float third = 1.0f / 3.0f;

        for (int s = 1; s < TFc; s++) {
            float u, k1, k2, k3, k4;

            u = ftanh(dot64p(s_in, w1p) + bo1); s_u[h] = u; ODEBAR();
            k1 = ftanh(dot64p(s_u, w2p) + bo2);
            s_in[h] = fmaf(dt * third, k1, yv); ODEBAR();

            u = ftanh(dot64p(s_in, w1p) + bo1); s_u[h] = u; ODEBAR();
            k2 = ftanh(dot64p(s_u, w2p) + bo2);
            s_in[h] = yv + dt * (k2 - third * k1); ODEBAR();

            u = ftanh(dot64p(s_in, w1p) + bo1); s_u[h] = u; ODEBAR();
            k3 = ftanh(dot64p(s_u, w2p) + bo2);
            s_in[h] = yv + dt * (k1 - k2 + k3); ODEBAR();

            u = ftanh(dot64p(s_in, w1p) + bo1); s_u[h] = u; ODEBAR();
            k4 = ftanh(dot64p(s_u, w2p) + bo2);
            yv = yv + dt * 0.125f * (k1 + 3.f * (k2 + k3) + k4);
            s_in[h] = yv; s_traj[s][h] = yv; ODEBAR();
        }
    }
    __syncthreads();

    // predictions: pred[tf] = traj[tf] . W_out + b_out (4 warps)
    {
        int w = tid >> 5, lane = tid & 31;
        for (int tf = w; tf < TFc; tf += 4) {
            float v = s_traj[tf][lane] * s_wout[lane]
                    + s_traj[tf][lane + 32] * s_wout[lane + 32];
            #pragma unroll
            for (int off = 16; off; off >>= 1) v += __shfl_xor_sync(0xffffffffu, v, off);
            if (lane == 0) s_pred[tf] = v + bout;
        }
    }
    __syncthreads();

    // out[b][n][tf] = pred[tf] (node-constant)
    float* ob = out + b * (Nc * TFc);
    for (int i = tid; i < Nc * TFc; i += 128)
        ob[i] = s_pred[i % TFc];
}

extern "C" void kernel_launch(void* const* d_in, const int* in_sizes, int n_in,
                              void* d_out, int out_size)
{
    const float* x     = (const float*)d_in[0];
    const float* W_s1  = (const float*)d_in[1];
    const float* b_s1  = (const float*)d_in[2];
    const float* W_s2  = (const float*)d_in[3];
    const float* b_s2  = (const float*)d_in[4];
    const float* Wa1   = (const float*)d_in[5];
    const float* ba1   = (const float*)d_in[6];
    const float* Wa2   = (const float*)d_in[7];
    const float* W_ih  = (const float*)d_in[9];
    const float* b_ih  = (const float*)d_in[11];
    const float* b_hh  = (const float*)d_in[12];
    const float* W_o1  = (const float*)d_in[13];
    const float* b_o1  = (const float*)d_in[14];
    const float* W_o2  = (const float*)d_in[15];
    const float* b_o2  = (const float*)d_in[16];
    const float* W_out = (const float*)d_in[17];
    const float* b_out = (const float*)d_in[18];

    dim3 gridA(NSL, Bc);
    front_kernel<<<gridA, 128>>>(x, W_s1, b_s1, W_s2, b_s2, Wa1, ba1, Wa2);
    ode_kernel<<<Bc, 128>>>(W_ih, b_ih, b_hh,
                            W_o1, b_o1, W_o2, b_o2,
                            W_out, b_out, (float*)d_out);
}